// round 2
// baseline (speedup 1.0000x reference)
#include <cuda_runtime.h>

#define Nn 50000
#define Ee 640000
#define Hh 128

// scratch for segment_sum(m_ij)  — __device__ global (no allocs allowed)
__device__ float g_msg[Nn * Hh];

__device__ __forceinline__ float silu_f(float v) {
    return v / (1.f + __expf(-v));
}

union U64F2 { unsigned long long u; float2 f; };

// Register-blocked fused GEMM: C[64 x 128] += A[64 x K] * B[K x 128]
// A in SMEM (row stride AW), B streamed from gmem (L2-resident) through a
// double-buffered SMEM staging tile. 128 threads, each owns an 8x8 C tile,
// accumulated as packed f32x2 pairs via fma.rn.f32x2 (2x fp32 FFMA rate on sm_103a).
template <int AW>
__device__ __forceinline__ void gemm_tile(
    const float* sA, float* sB, const float* __restrict__ Bg, int K,
    int ty, int tx, int tid, unsigned long long acc2[8][4])
{
#pragma unroll
    for (int r = 0; r < 8; r++)
#pragma unroll
        for (int cp = 0; cp < 4; cp++) acc2[r][cp] = 0ull;

    const int nCh = (K + 15) >> 4;

    // prologue: stage chunk 0 into buffer 0
    {
#pragma unroll
        for (int s = 0; s < 4; s++) {
            int idx = tid + s * 128;
            int row = idx >> 5, col = (idx & 31) * 4;
            float4 v = make_float4(0.f, 0.f, 0.f, 0.f);
            if (row < K) v = *(const float4*)(Bg + row * 128 + col);
            *(float4*)(sB + row * 128 + col) = v;
        }
    }
    __syncthreads();

    for (int c = 0; c < nCh; c++) {
        // prefetch next chunk into the other buffer
        if (c + 1 < nCh) {
            int base = (c + 1) * 16;
            float* dB = sB + ((c + 1) & 1) * 2048;
#pragma unroll
            for (int s = 0; s < 4; s++) {
                int idx = tid + s * 128;
                int row = idx >> 5, col = (idx & 31) * 4;
                int k = base + row;
                float4 v = make_float4(0.f, 0.f, 0.f, 0.f);
                if (k < K) v = *(const float4*)(Bg + k * 128 + col);
                *(float4*)(dB + row * 128 + col) = v;
            }
        }
        const float* A  = sA + (ty * 8) * AW + c * 16;
        const float* Bb = sB + (c & 1) * 2048;
#pragma unroll
        for (int kk = 0; kk < 16; kk++) {
            unsigned long long b2[4];
            const ulonglong2* bp = (const ulonglong2*)(Bb + kk * 128 + tx * 8);
            ulonglong2 t0 = bp[0];
            ulonglong2 t1 = bp[1];
            b2[0] = t0.x; b2[1] = t0.y; b2[2] = t1.x; b2[3] = t1.y;
#pragma unroll
            for (int r = 0; r < 8; r++) {
                float a = A[r * AW + kk];
                unsigned long long a2;
                asm("mov.b64 %0, {%1, %1};" : "=l"(a2) : "f"(a));
#pragma unroll
                for (int cp = 0; cp < 4; cp++)
                    asm("fma.rn.f32x2 %0, %1, %2, %0;"
                        : "+l"(acc2[r][cp]) : "l"(a2), "l"(b2[cp]));
            }
        }
        __syncthreads();
    }
}

// bias + SiLU, write result back into sA[e][0..127] for the next layer
template <int AW>
__device__ __forceinline__ void bias_silu_store(
    unsigned long long acc2[8][4], const float* __restrict__ bias,
    float* sA, int ty, int tx)
{
#pragma unroll
    for (int r = 0; r < 8; r++) {
        float* row = sA + (ty * 8 + r) * AW + tx * 8;
#pragma unroll
        for (int cp = 0; cp < 4; cp++) {
            U64F2 u; u.u = acc2[r][cp];
            int f = tx * 8 + cp * 2;
            row[cp * 2]     = silu_f(u.f.x + bias[f]);
            row[cp * 2 + 1] = silu_f(u.f.y + bias[f + 1]);
        }
    }
}

// ---------------------------------------------------------------------------
// init: x_out = x ; g_msg = 0
__global__ void init_kernel(const float* __restrict__ x, float* __restrict__ xo) {
    int idx = blockIdx.x * 256 + threadIdx.x;
    if (idx < Nn * 3) xo[idx] = x[idx];
    if (idx < Nn * Hh) g_msg[idx] = 0.f;
}

// ---------------------------------------------------------------------------
// edge kernel: 64 edges per CTA, fully fused edge MLP + coord MLP + scatters
__global__ __launch_bounds__(128, 2) void edge_kernel(
    const float* __restrict__ h, const float* __restrict__ x, const int* __restrict__ ei,
    const float* __restrict__ We1, const float* __restrict__ be1,
    const float* __restrict__ We2, const float* __restrict__ be2,
    const float* __restrict__ Wc1, const float* __restrict__ bc1,
    const float* __restrict__ Wc2, float* __restrict__ xo)
{
    const int AW = 277;                    // odd-ish stride: conflict-free A column reads
    extern __shared__ float sm[];
    float* sA   = sm;                      // 64 * 277 floats
    float* sB   = sm + 64 * AW;            // 2 * 16 * 128 floats
    float* sRel = sB + 4096;               // 64 * 3
    int*   sDst = (int*)(sRel + 192);      // 64

    int tid = threadIdx.x;
    int ty = tid >> 4, tx = tid & 15;
    int e0 = blockIdx.x * 64;

    // gather: sA[i] = [ h[src] (0..127) | h[dst] (128..255) | dist^2 (256) | 0 pad ]
    for (int idx = tid; idx < 64 * 64; idx += 128) {
        int i = idx >> 6, q = idx & 63;
        int ge = e0 + i;
        int node = (q < 32) ? ei[ge] : ei[Ee + ge];
        float4 v = *(const float4*)(h + (size_t)node * Hh + (q & 31) * 4);
        int col = (q < 32) ? (q * 4) : (Hh + (q - 32) * 4);
        float* p = sA + i * AW + col;
        p[0] = v.x; p[1] = v.y; p[2] = v.z; p[3] = v.w;
    }
    if (tid < 64) {
        int ge = e0 + tid;
        int s = ei[ge], d = ei[Ee + ge];
        float rx = x[s * 3 + 0] - x[d * 3 + 0];
        float ry = x[s * 3 + 1] - x[d * 3 + 1];
        float rz = x[s * 3 + 2] - x[d * 3 + 2];
        sRel[tid * 3 + 0] = rx; sRel[tid * 3 + 1] = ry; sRel[tid * 3 + 2] = rz;
        sA[tid * AW + 256] = rx * rx + ry * ry + rz * rz;
#pragma unroll
        for (int k = 257; k < 272; k++) sA[tid * AW + k] = 0.f;   // K padded to 272
        sDst[tid] = d;
    }
    // (first barrier inside gemm_tile covers the gather)

    unsigned long long acc2[8][4];

    // layer 1: [64 x 257] @ We1 -> SiLU
    gemm_tile<AW>(sA, sB, We1, 257, ty, tx, tid, acc2);
    bias_silu_store<AW>(acc2, be1, sA, ty, tx);

    // layer 2: [64 x 128] @ We2 -> SiLU  => m_ij (left in sA)
    gemm_tile<AW>(sA, sB, We2, 128, ty, tx, tid, acc2);
    bias_silu_store<AW>(acc2, be2, sA, ty, tx);

    // coord MLP: SiLU(m_ij @ Wc1 + bc1) . Wc2  => per-edge scalar w
    gemm_tile<AW>(sA, sB, Wc1, 128, ty, tx, tid, acc2);

    float partial[8];
#pragma unroll
    for (int r = 0; r < 8; r++) partial[r] = 0.f;
#pragma unroll
    for (int r = 0; r < 8; r++) {
#pragma unroll
        for (int cp = 0; cp < 4; cp++) {
            U64F2 u; u.u = acc2[r][cp];
            int f = tx * 8 + cp * 2;
            partial[r] += silu_f(u.f.x + bc1[f])     * Wc2[f];
            partial[r] += silu_f(u.f.y + bc1[f + 1]) * Wc2[f + 1];
        }
    }
#pragma unroll
    for (int off = 8; off > 0; off >>= 1)
#pragma unroll
        for (int r = 0; r < 8; r++)
            partial[r] += __shfl_xor_sync(0xffffffffu, partial[r], off);

    if (tx == 0) {
#pragma unroll
        for (int r = 0; r < 8; r++) {
            int i = ty * 8 + r;
            float w = partial[r];
            int d = sDst[i];
            atomicAdd(xo + (size_t)d * 3 + 0, sRel[i * 3 + 0] * w);
            atomicAdd(xo + (size_t)d * 3 + 1, sRel[i * 3 + 1] * w);
            atomicAdd(xo + (size_t)d * 3 + 2, sRel[i * 3 + 2] * w);
        }
    }

    // msg_agg scatter: m_ij still in sA; vectorized global reductions
    for (int idx = tid; idx < 64 * 32; idx += 128) {
        int i = idx >> 5, q = (idx & 31) * 4;
        const float* p = sA + i * AW + q;
        float v0 = p[0], v1 = p[1], v2 = p[2], v3 = p[3];
        float* gp = g_msg + (size_t)sDst[i] * Hh + q;
        asm volatile("red.global.add.v4.f32 [%0], {%1, %2, %3, %4};"
                     :: "l"(gp), "f"(v0), "f"(v1), "f"(v2), "f"(v3) : "memory");
    }
}

// ---------------------------------------------------------------------------
// node kernel: h_out = h + Wn2 @ SiLU([h | msg_agg] @ Wn1 + bn1) + bn2
__global__ __launch_bounds__(128, 2) void node_kernel(
    const float* __restrict__ h,
    const float* __restrict__ Wn1, const float* __restrict__ bn1,
    const float* __restrict__ Wn2, const float* __restrict__ bn2,
    float* __restrict__ ho)
{
    const int AW = 261;
    extern __shared__ float sm[];
    float* sA = sm;                 // 64 * 261
    float* sB = sm + 64 * AW;       // 4096
    int tid = threadIdx.x;
    int ty = tid >> 4, tx = tid & 15;
    int n0 = blockIdx.x * 64;

    for (int idx = tid; idx < 64 * 64; idx += 128) {
        int i = idx >> 6, q = idx & 63;
        int n = n0 + i;
        float4 v = make_float4(0.f, 0.f, 0.f, 0.f);
        if (n < Nn) {
            const float* src = (q < 32) ? (h + (size_t)n * Hh + q * 4)
                                        : (g_msg + (size_t)n * Hh + (q - 32) * 4);
            v = *(const float4*)src;
        }
        int col = (q < 32) ? q * 4 : (Hh + (q - 32) * 4);
        float* p = sA + i * AW + col;
        p[0] = v.x; p[1] = v.y; p[2] = v.z; p[3] = v.w;
    }

    unsigned long long acc2[8][4];
    gemm_tile<AW>(sA, sB, Wn1, 256, ty, tx, tid, acc2);
    bias_silu_store<AW>(acc2, bn1, sA, ty, tx);
    gemm_tile<AW>(sA, sB, Wn2, 128, ty, tx, tid, acc2);

#pragma unroll
    for (int r = 0; r < 8; r++) {
        int n = n0 + ty * 8 + r;
        if (n < Nn) {
#pragma unroll
            for (int cp = 0; cp < 4; cp++) {
                U64F2 u; u.u = acc2[r][cp];
                int f = tx * 8 + cp * 2;
                float2 o;
                o.x = u.f.x + bn2[f]     + h[(size_t)n * Hh + f];
                o.y = u.f.y + bn2[f + 1] + h[(size_t)n * Hh + f + 1];
                *(float2*)(ho + (size_t)n * Hh + f) = o;
            }
        }
    }
}

// ---------------------------------------------------------------------------
static const int EDGE_SMEM = (64 * 277 + 4096 + 192 + 64) * 4;   // 88320 B
static const int NODE_SMEM = (64 * 261 + 4096) * 4;              // 83200 B

extern "C" void kernel_launch(void* const* d_in, const int* in_sizes, int n_in,
                              void* d_out, int out_size) {
    const float* h   = (const float*)d_in[0];
    const float* x   = (const float*)d_in[1];
    const int*   ei  = (const int*)d_in[2];
    const float* We1 = (const float*)d_in[3];
    const float* be1 = (const float*)d_in[4];
    const float* We2 = (const float*)d_in[5];
    const float* be2 = (const float*)d_in[6];
    const float* Wc1 = (const float*)d_in[7];
    const float* bc1 = (const float*)d_in[8];
    const float* Wc2 = (const float*)d_in[9];
    const float* Wn1 = (const float*)d_in[10];
    const float* bn1 = (const float*)d_in[11];
    const float* Wn2 = (const float*)d_in[12];
    const float* bn2 = (const float*)d_in[13];

    float* out = (float*)d_out;
    float* ho = out;                         // h_out: N*H
    float* xo = out + (size_t)Nn * Hh;       // x_out: N*3

    cudaFuncSetAttribute(edge_kernel, cudaFuncAttributeMaxDynamicSharedMemorySize, EDGE_SMEM);
    cudaFuncSetAttribute(node_kernel, cudaFuncAttributeMaxDynamicSharedMemorySize, NODE_SMEM);

    init_kernel<<<(Nn * Hh + 255) / 256, 256>>>(x, xo);
    edge_kernel<<<Ee / 64, 128, EDGE_SMEM>>>(h, x, ei,
                                             We1, be1, We2, be2, Wc1, bc1, Wc2, xo);
    node_kernel<<<(Nn + 63) / 64, 128, NODE_SMEM>>>(h, Wn1, bn1, Wn2, bn2, ho);
}

// round 3
// speedup vs baseline: 1.7771x; 1.7771x over previous
#include <cuda_runtime.h>

#define Nn 50000
#define Ee 640000
#define Hh 128
#define CHUNK 32

// device-global scratch (no allocs allowed)
__device__ float g_msg[Nn * Hh];
__device__ float g_hs[Nn * Hh];   // h @ We1[0:128]   + be1
__device__ float g_hd[Nn * Hh];   // h @ We1[128:256]

__device__ __forceinline__ float silu_f(float v) {
    return v / (1.f + __expf(-v));
}

union U64F2 { unsigned long long u; float2 f; };

__device__ __forceinline__ void cp_async16(float* dst, const float* src) {
    unsigned u = (unsigned)__cvta_generic_to_shared(dst);
    asm volatile("cp.async.ca.shared.global [%0], [%1], 16;" :: "r"(u), "l"(src));
}
__device__ __forceinline__ void cp_commit() { asm volatile("cp.async.commit_group;"); }
template<int P> __device__ __forceinline__ void cp_wait() {
    asm volatile("cp.async.wait_group %0;" :: "n"(P));
}

// stage one CHUNK x 128 fp32 slab of B into smem via cp.async (16 KB)
__device__ __forceinline__ void stage_b(float* dst, const float* __restrict__ src, int tid) {
#pragma unroll
    for (int s = 0; s < 8; s++) {
        int idx = tid + s * 128;
        int row = idx >> 5, col = (idx & 31) * 4;
        cp_async16(dst + row * 128 + col, src + row * 128 + col);
    }
}

// Register-blocked fused GEMM: C[64 x 128] += A[64 x K] * B[K x 128]
// A in SMEM (row stride AW, multiple of 4), B streamed via double-buffered
// cp.async staging. 128 threads, each owns an 8x8 C tile as packed f32x2.
// K must be a multiple of 32.
template <int AW>
__device__ __forceinline__ void gemm_tile(
    const float* sA, float* sB, const float* __restrict__ Bg, int K,
    int ty, int tx, int tid, unsigned long long acc2[8][4])
{
#pragma unroll
    for (int r = 0; r < 8; r++)
#pragma unroll
        for (int cp = 0; cp < 4; cp++) acc2[r][cp] = 0ull;

    const int nCh = K / CHUNK;

    stage_b(sB, Bg, tid);
    cp_commit();

    for (int c = 0; c < nCh; c++) {
        if (c + 1 < nCh) {
            stage_b(sB + ((c + 1) & 1) * (CHUNK * 128), Bg + (c + 1) * CHUNK * 128, tid);
            cp_commit();
            cp_wait<1>();
        } else {
            cp_wait<0>();
        }
        __syncthreads();   // chunk c visible to all (also covers caller's sA writes on c==0)

        const float* A  = sA + (ty * 8) * AW + c * CHUNK;
        const float* Bb = sB + (c & 1) * (CHUNK * 128);
#pragma unroll
        for (int kq = 0; kq < CHUNK / 4; kq++) {
            float4 a4[8];
#pragma unroll
            for (int r = 0; r < 8; r++)
                a4[r] = *(const float4*)(A + r * AW + kq * 4);
#pragma unroll
            for (int k2 = 0; k2 < 4; k2++) {
                const ulonglong2* bp =
                    (const ulonglong2*)(Bb + (kq * 4 + k2) * 128 + tx * 8);
                ulonglong2 t0 = bp[0];
                ulonglong2 t1 = bp[1];
                unsigned long long b2[4] = { t0.x, t0.y, t1.x, t1.y };
#pragma unroll
                for (int r = 0; r < 8; r++) {
                    float a = (k2 == 0) ? a4[r].x : (k2 == 1) ? a4[r].y
                             : (k2 == 2) ? a4[r].z : a4[r].w;
                    unsigned long long a2;
                    asm("mov.b64 %0, {%1, %1};" : "=l"(a2) : "f"(a));
#pragma unroll
                    for (int cp = 0; cp < 4; cp++)
                        asm("fma.rn.f32x2 %0, %1, %2, %0;"
                            : "+l"(acc2[r][cp]) : "l"(a2), "l"(b2[cp]));
                }
            }
        }
        __syncthreads();   // all reads of buffer (c&1) done before it is restaged
    }
}

// bias + SiLU, write back into sA[.. 0..127] for the next layer
template <int AW>
__device__ __forceinline__ void bias_silu_store(
    unsigned long long acc2[8][4], const float* __restrict__ bias,
    float* sA, int ty, int tx)
{
#pragma unroll
    for (int r = 0; r < 8; r++) {
        float* row = sA + (ty * 8 + r) * AW + tx * 8;
#pragma unroll
        for (int cp = 0; cp < 4; cp++) {
            U64F2 u; u.u = acc2[r][cp];
            int f = tx * 8 + cp * 2;
            row[cp * 2]     = silu_f(u.f.x + bias[f]);
            row[cp * 2 + 1] = silu_f(u.f.y + bias[f + 1]);
        }
    }
}

// ---------------------------------------------------------------------------
__global__ void init_kernel(const float* __restrict__ x, float* __restrict__ xo) {
    int idx = blockIdx.x * 256 + threadIdx.x;
    if (idx < Nn * 3) xo[idx] = x[idx];
    if (idx < Nn * Hh) g_msg[idx] = 0.f;
}

// ---------------------------------------------------------------------------
// precompute: g_hs = h @ We1[0:128] + be1 ; g_hd = h @ We1[128:256]
__global__ __launch_bounds__(128, 3) void pre_kernel(
    const float* __restrict__ h, const float* __restrict__ We1,
    const float* __restrict__ be1)
{
    const int AW = 132;
    extern __shared__ float sm[];
    float* sA = sm;                  // 64*132
    float* sB = sm + 64 * AW;        // 2*32*128

    int tid = threadIdx.x;
    int ty = tid >> 4, tx = tid & 15;
    int n0 = blockIdx.x * 64;

    for (int idx = tid; idx < 64 * 32; idx += 128) {
        int i = idx >> 5, q = (idx & 31) * 4;
        int n = n0 + i;
        float4 v = make_float4(0.f, 0.f, 0.f, 0.f);
        if (n < Nn) v = *(const float4*)(h + (size_t)n * Hh + q);
        *(float4*)(sA + i * AW + q) = v;
    }

    unsigned long long acc2[8][4];

    gemm_tile<AW>(sA, sB, We1, Hh, ty, tx, tid, acc2);
#pragma unroll
    for (int r = 0; r < 8; r++) {
        int n = n0 + ty * 8 + r;
        if (n < Nn) {
#pragma unroll
            for (int cp = 0; cp < 4; cp++) {
                U64F2 u; u.u = acc2[r][cp];
                int f = tx * 8 + cp * 2;
                float2 o; o.x = u.f.x + be1[f]; o.y = u.f.y + be1[f + 1];
                *(float2*)(g_hs + (size_t)n * Hh + f) = o;
            }
        }
    }

    gemm_tile<AW>(sA, sB, We1 + 128 * Hh, Hh, ty, tx, tid, acc2);
#pragma unroll
    for (int r = 0; r < 8; r++) {
        int n = n0 + ty * 8 + r;
        if (n < Nn) {
#pragma unroll
            for (int cp = 0; cp < 4; cp++) {
                U64F2 u; u.u = acc2[r][cp];
                int f = tx * 8 + cp * 2;
                *(float2*)(g_hd + (size_t)n * Hh + f) = u.f;
            }
        }
    }
}

// ---------------------------------------------------------------------------
// edge kernel: layer1 via precomputed gathers; fused layer2 + coord MLP + scatters
__global__ __launch_bounds__(128, 3) void edge_kernel(
    const float* __restrict__ x, const int* __restrict__ ei,
    const float* __restrict__ We1,                      // row 256 = dist^2 weights
    const float* __restrict__ We2, const float* __restrict__ be2,
    const float* __restrict__ Wc1, const float* __restrict__ bc1,
    const float* __restrict__ Wc2, float* __restrict__ xo)
{
    const int AW = 132;
    extern __shared__ float sm[];
    float* sA   = sm;                          // 64*132
    float* sB   = sm + 64 * AW;                // 2*32*128 = 8192
    float* sRel = sB + 8192;                   // 192
    float* sD2  = sRel + 192;                  // 64
    float* sW   = sD2 + 64;                    // 128 (We1 row 256)
    int*   sSrc = (int*)(sW + 128);            // 64
    int*   sDst = sSrc + 64;                   // 64

    int tid = threadIdx.x;
    int ty = tid >> 4, tx = tid & 15;
    int e0 = blockIdx.x * 64;

    if (tid < 64) {
        int ge = e0 + tid;
        int s = ei[ge], d = ei[Ee + ge];
        float rx = x[s * 3 + 0] - x[d * 3 + 0];
        float ry = x[s * 3 + 1] - x[d * 3 + 1];
        float rz = x[s * 3 + 2] - x[d * 3 + 2];
        sRel[tid * 3 + 0] = rx; sRel[tid * 3 + 1] = ry; sRel[tid * 3 + 2] = rz;
        sD2[tid] = rx * rx + ry * ry + rz * rz;
        sSrc[tid] = s; sDst[tid] = d;
    } else if (tid < 96) {
        int t = tid - 64;
        *(float4*)(sW + t * 4) = *(const float4*)(We1 + 256 * Hh + t * 4);
    }
    __syncthreads();

    // layer-1 output directly: sA[i] = silu(hs[src] + hd[dst] + d2 * w256)
    for (int idx = tid; idx < 64 * 32; idx += 128) {
        int i = idx >> 5, q = (idx & 31) * 4;
        int s = sSrc[i], d = sDst[i];
        float d2 = sD2[i];
        float4 a = *(const float4*)(g_hs + (size_t)s * Hh + q);
        float4 b = *(const float4*)(g_hd + (size_t)d * Hh + q);
        float4 w = *(const float4*)(sW + q);
        float* p = sA + i * AW + q;
        p[0] = silu_f(a.x + b.x + d2 * w.x);
        p[1] = silu_f(a.y + b.y + d2 * w.y);
        p[2] = silu_f(a.z + b.z + d2 * w.z);
        p[3] = silu_f(a.w + b.w + d2 * w.w);
    }
    // (first barrier inside gemm_tile covers these writes)

    unsigned long long acc2[8][4];

    // layer 2: m_ij = silu([64x128] @ We2 + be2), left in sA
    gemm_tile<AW>(sA, sB, We2, Hh, ty, tx, tid, acc2);
    bias_silu_store<AW>(acc2, be2, sA, ty, tx);

    // coord MLP: w = silu(m_ij @ Wc1 + bc1) . Wc2
    gemm_tile<AW>(sA, sB, Wc1, Hh, ty, tx, tid, acc2);

    float partial[8];
#pragma unroll
    for (int r = 0; r < 8; r++) partial[r] = 0.f;
#pragma unroll
    for (int r = 0; r < 8; r++)
#pragma unroll
        for (int cp = 0; cp < 4; cp++) {
            U64F2 u; u.u = acc2[r][cp];
            int f = tx * 8 + cp * 2;
            partial[r] += silu_f(u.f.x + bc1[f])     * Wc2[f];
            partial[r] += silu_f(u.f.y + bc1[f + 1]) * Wc2[f + 1];
        }
#pragma unroll
    for (int off = 8; off > 0; off >>= 1)
#pragma unroll
        for (int r = 0; r < 8; r++)
            partial[r] += __shfl_xor_sync(0xffffffffu, partial[r], off);

    if (tx == 0) {
#pragma unroll
        for (int r = 0; r < 8; r++) {
            int i = ty * 8 + r;
            float w = partial[r];
            int d = sDst[i];
            atomicAdd(xo + (size_t)d * 3 + 0, sRel[i * 3 + 0] * w);
            atomicAdd(xo + (size_t)d * 3 + 1, sRel[i * 3 + 1] * w);
            atomicAdd(xo + (size_t)d * 3 + 2, sRel[i * 3 + 2] * w);
        }
    }

    // msg_agg scatter: m_ij still in sA; vectorized global reductions
    for (int idx = tid; idx < 64 * 32; idx += 128) {
        int i = idx >> 5, q = (idx & 31) * 4;
        const float* p = sA + i * AW + q;
        float v0 = p[0], v1 = p[1], v2 = p[2], v3 = p[3];
        float* gp = g_msg + (size_t)sDst[i] * Hh + q;
        asm volatile("red.global.add.v4.f32 [%0], {%1, %2, %3, %4};"
                     :: "l"(gp), "f"(v0), "f"(v1), "f"(v2), "f"(v3) : "memory");
    }
}

// ---------------------------------------------------------------------------
// node kernel: h_out = h + Wn2 @ SiLU([h | msg_agg] @ Wn1 + bn1) + bn2
__global__ __launch_bounds__(128, 2) void node_kernel(
    const float* __restrict__ h,
    const float* __restrict__ Wn1, const float* __restrict__ bn1,
    const float* __restrict__ Wn2, const float* __restrict__ bn2,
    float* __restrict__ ho)
{
    const int AW = 260;
    extern __shared__ float sm[];
    float* sA = sm;                 // 64 * 260
    float* sB = sm + 64 * AW;       // 8192
    int tid = threadIdx.x;
    int ty = tid >> 4, tx = tid & 15;
    int n0 = blockIdx.x * 64;

    for (int idx = tid; idx < 64 * 64; idx += 128) {
        int i = idx >> 6, q = idx & 63;
        int n = n0 + i;
        float4 v = make_float4(0.f, 0.f, 0.f, 0.f);
        if (n < Nn) {
            const float* src = (q < 32) ? (h + (size_t)n * Hh + q * 4)
                                        : (g_msg + (size_t)n * Hh + (q - 32) * 4);
            v = *(const float4*)src;
        }
        int col = (q < 32) ? q * 4 : (Hh + (q - 32) * 4);
        *(float4*)(sA + i * AW + col) = v;
    }

    unsigned long long acc2[8][4];
    gemm_tile<AW>(sA, sB, Wn1, 256, ty, tx, tid, acc2);
    bias_silu_store<AW>(acc2, bn1, sA, ty, tx);
    gemm_tile<AW>(sA, sB, Wn2, Hh, ty, tx, tid, acc2);

#pragma unroll
    for (int r = 0; r < 8; r++) {
        int n = n0 + ty * 8 + r;
        if (n < Nn) {
#pragma unroll
            for (int cp = 0; cp < 4; cp++) {
                U64F2 u; u.u = acc2[r][cp];
                int f = tx * 8 + cp * 2;
                float2 o;
                o.x = u.f.x + bn2[f]     + h[(size_t)n * Hh + f];
                o.y = u.f.y + bn2[f + 1] + h[(size_t)n * Hh + f + 1];
                *(float2*)(ho + (size_t)n * Hh + f) = o;
            }
        }
    }
}

// ---------------------------------------------------------------------------
static const int PRE_SMEM  = (64 * 132 + 8192) * 4;                         // 66560
static const int EDGE_SMEM = (64 * 132 + 8192 + 192 + 64 + 128 + 128) * 4;  // 68608
static const int NODE_SMEM = (64 * 260 + 8192) * 4;                         // 99328

extern "C" void kernel_launch(void* const* d_in, const int* in_sizes, int n_in,
                              void* d_out, int out_size) {
    const float* h   = (const float*)d_in[0];
    const float* x   = (const float*)d_in[1];
    const int*   ei  = (const int*)d_in[2];
    const float* We1 = (const float*)d_in[3];
    const float* be1 = (const float*)d_in[4];
    const float* We2 = (const float*)d_in[5];
    const float* be2 = (const float*)d_in[6];
    const float* Wc1 = (const float*)d_in[7];
    const float* bc1 = (const float*)d_in[8];
    const float* Wc2 = (const float*)d_in[9];
    const float* Wn1 = (const float*)d_in[10];
    const float* bn1 = (const float*)d_in[11];
    const float* Wn2 = (const float*)d_in[12];
    const float* bn2 = (const float*)d_in[13];

    float* out = (float*)d_out;
    float* ho = out;                         // h_out: N*H
    float* xo = out + (size_t)Nn * Hh;       // x_out: N*3

    cudaFuncSetAttribute(pre_kernel,  cudaFuncAttributeMaxDynamicSharedMemorySize, PRE_SMEM);
    cudaFuncSetAttribute(edge_kernel, cudaFuncAttributeMaxDynamicSharedMemorySize, EDGE_SMEM);
    cudaFuncSetAttribute(node_kernel, cudaFuncAttributeMaxDynamicSharedMemorySize, NODE_SMEM);

    init_kernel<<<(Nn * Hh + 255) / 256, 256>>>(x, xo);
    pre_kernel<<<(Nn + 63) / 64, 128, PRE_SMEM>>>(h, We1, be1);
    edge_kernel<<<Ee / 64, 128, EDGE_SMEM>>>(x, ei, We1, We2, be2, Wc1, bc1, Wc2, xo);
    node_kernel<<<(Nn + 63) / 64, 128, NODE_SMEM>>>(h, Wn1, bn1, Wn2, bn2, ho);
}

// round 4
// speedup vs baseline: 1.9275x; 1.0847x over previous
#include <cuda_runtime.h>

#define Nn 50000
#define Ee 640000
#define Hh 128
#define CHUNK 32

// device-global scratch (no allocs allowed)
__device__ float g_msg[Nn * Hh];
__device__ float g_hs[Nn * Hh];   // h @ We1[0:128]   + be1
__device__ float g_hd[Nn * Hh];   // h @ We1[128:256]

__device__ __forceinline__ float silu_f(float v) {
    return v / (1.f + __expf(-v));
}

union U64F2 { unsigned long long u; float2 f; };

// column owned by (tx, cp): cp 0,1 -> tx*4 + cp*2 ; cp 2,3 -> 64 + tx*4 + (cp-2)*2
__device__ __forceinline__ int colof(int tx, int cp) {
    return (cp < 2) ? (tx * 4 + cp * 2) : (64 + tx * 4 + (cp - 2) * 2);
}

__device__ __forceinline__ void cp_async16(float* dst, const float* src) {
    unsigned u = (unsigned)__cvta_generic_to_shared(dst);
    asm volatile("cp.async.ca.shared.global [%0], [%1], 16;" :: "r"(u), "l"(src));
}
__device__ __forceinline__ void cp_commit() { asm volatile("cp.async.commit_group;"); }
template<int P> __device__ __forceinline__ void cp_wait() {
    asm volatile("cp.async.wait_group %0;" :: "n"(P));
}

// stage one CHUNK x 128 fp32 slab of B into smem via cp.async (16 KB)
__device__ __forceinline__ void stage_b(float* dst, const float* __restrict__ src, int tid) {
#pragma unroll
    for (int s = 0; s < 8; s++) {
        int idx = tid + s * 128;
        int row = idx >> 5, col = (idx & 31) * 4;
        cp_async16(dst + row * 128 + col, src + row * 128 + col);
    }
}

// Register-blocked fused GEMM: C[64 x 128] += A[64 x K] * B[K x 128]
// A in SMEM (row stride AW, multiple of 4), B streamed via double-buffered
// cp.async staging. 128 threads; thread (ty,tx) owns rows ty*8..+7 and the
// 8 columns {tx*4..+3, 64+tx*4..+3} (conflict-free 4-word stride across an
// 8-lane LDS phase). Accumulators are packed f32x2 (fma.rn.f32x2: 2x FFMA rate).
// K must be a multiple of 32. If ZERO_INIT==false, accumulates into acc2.
template <int AW, bool ZERO_INIT>
__device__ __forceinline__ void gemm_tile(
    const float* sA, float* sB, const float* __restrict__ Bg, int K,
    int ty, int tx, int tid, unsigned long long acc2[8][4])
{
    if (ZERO_INIT) {
#pragma unroll
        for (int r = 0; r < 8; r++)
#pragma unroll
            for (int cp = 0; cp < 4; cp++) acc2[r][cp] = 0ull;
    }

    const int nCh = K / CHUNK;

    stage_b(sB, Bg, tid);
    cp_commit();

    for (int c = 0; c < nCh; c++) {
        if (c + 1 < nCh) {
            stage_b(sB + ((c + 1) & 1) * (CHUNK * 128), Bg + (c + 1) * CHUNK * 128, tid);
            cp_commit();
            cp_wait<1>();
        } else {
            cp_wait<0>();
        }
        __syncthreads();   // chunk c visible (also covers caller's sA writes on c==0)

        const float* A  = sA + (ty * 8) * AW + c * CHUNK;
        const float* Bb = sB + (c & 1) * (CHUNK * 128);
#pragma unroll
        for (int kq = 0; kq < CHUNK / 4; kq++) {
            float4 a4[8];
#pragma unroll
            for (int r = 0; r < 8; r++)
                a4[r] = *(const float4*)(A + r * AW + kq * 4);
#pragma unroll
            for (int k2 = 0; k2 < 4; k2++) {
                const float* brow = Bb + (kq * 4 + k2) * 128;
                ulonglong2 t0 = *(const ulonglong2*)(brow + tx * 4);       // cols tx*4..+3
                ulonglong2 t1 = *(const ulonglong2*)(brow + 64 + tx * 4);  // cols 64+tx*4..+3
                unsigned long long b2[4] = { t0.x, t0.y, t1.x, t1.y };
#pragma unroll
                for (int r = 0; r < 8; r++) {
                    float a = (k2 == 0) ? a4[r].x : (k2 == 1) ? a4[r].y
                             : (k2 == 2) ? a4[r].z : a4[r].w;
                    unsigned long long a2;
                    asm("mov.b64 %0, {%1, %1};" : "=l"(a2) : "f"(a));
#pragma unroll
                    for (int cp = 0; cp < 4; cp++)
                        asm("fma.rn.f32x2 %0, %1, %2, %0;"
                            : "+l"(acc2[r][cp]) : "l"(a2), "l"(b2[cp]));
                }
            }
        }
        __syncthreads();   // all reads of buffer (c&1) done before restage
    }
}

// bias + SiLU, write back into sA[.. 0..127] (two conflict-free STS.128 per row)
template <int AW>
__device__ __forceinline__ void bias_silu_store(
    unsigned long long acc2[8][4], const float* __restrict__ bias,
    float* sA, int ty, int tx)
{
#pragma unroll
    for (int r = 0; r < 8; r++) {
        float* row = sA + (ty * 8 + r) * AW;
        U64F2 u0, u1;
        u0.u = acc2[r][0]; u1.u = acc2[r][1];
        float4 v0;
        v0.x = silu_f(u0.f.x + bias[tx * 4 + 0]);
        v0.y = silu_f(u0.f.y + bias[tx * 4 + 1]);
        v0.z = silu_f(u1.f.x + bias[tx * 4 + 2]);
        v0.w = silu_f(u1.f.y + bias[tx * 4 + 3]);
        *(float4*)(row + tx * 4) = v0;
        u0.u = acc2[r][2]; u1.u = acc2[r][3];
        float4 v1;
        v1.x = silu_f(u0.f.x + bias[64 + tx * 4 + 0]);
        v1.y = silu_f(u0.f.y + bias[64 + tx * 4 + 1]);
        v1.z = silu_f(u1.f.x + bias[64 + tx * 4 + 2]);
        v1.w = silu_f(u1.f.y + bias[64 + tx * 4 + 3]);
        *(float4*)(row + 64 + tx * 4) = v1;
    }
}

// ---------------------------------------------------------------------------
__global__ void init_kernel(const float* __restrict__ x, float* __restrict__ xo) {
    int idx = blockIdx.x * 256 + threadIdx.x;
    if (idx < Nn * 3) xo[idx] = x[idx];
    if (idx < Nn * Hh) g_msg[idx] = 0.f;
}

// ---------------------------------------------------------------------------
// precompute: g_hs = h @ We1[0:128] + be1 ; g_hd = h @ We1[128:256]
__global__ __launch_bounds__(128, 3) void pre_kernel(
    const float* __restrict__ h, const float* __restrict__ We1,
    const float* __restrict__ be1)
{
    const int AW = 132;
    extern __shared__ float sm[];
    float* sA = sm;                  // 64*132
    float* sB = sm + 64 * AW;        // 2*32*128

    int tid = threadIdx.x;
    int ty = tid >> 4, tx = tid & 15;
    int n0 = blockIdx.x * 64;

    for (int idx = tid; idx < 64 * 32; idx += 128) {
        int i = idx >> 5, q = (idx & 31) * 4;
        int n = n0 + i;
        float4 v = make_float4(0.f, 0.f, 0.f, 0.f);
        if (n < Nn) v = *(const float4*)(h + (size_t)n * Hh + q);
        *(float4*)(sA + i * AW + q) = v;
    }

    unsigned long long acc2[8][4];

    gemm_tile<AW, true>(sA, sB, We1, Hh, ty, tx, tid, acc2);
#pragma unroll
    for (int r = 0; r < 8; r++) {
        int n = n0 + ty * 8 + r;
        if (n < Nn) {
#pragma unroll
            for (int cp = 0; cp < 4; cp++) {
                U64F2 u; u.u = acc2[r][cp];
                int f = colof(tx, cp);
                float2 o; o.x = u.f.x + be1[f]; o.y = u.f.y + be1[f + 1];
                *(float2*)(g_hs + (size_t)n * Hh + f) = o;
            }
        }
    }

    gemm_tile<AW, true>(sA, sB, We1 + 128 * Hh, Hh, ty, tx, tid, acc2);
#pragma unroll
    for (int r = 0; r < 8; r++) {
        int n = n0 + ty * 8 + r;
        if (n < Nn) {
#pragma unroll
            for (int cp = 0; cp < 4; cp++) {
                U64F2 u; u.u = acc2[r][cp];
                *(float2*)(g_hd + (size_t)n * Hh + colof(tx, cp)) = u.f;
            }
        }
    }
}

// ---------------------------------------------------------------------------
// edge kernel: layer1 via precomputed gathers; fused layer2 + coord MLP + scatters
__global__ __launch_bounds__(128, 3) void edge_kernel(
    const float* __restrict__ x, const int* __restrict__ ei,
    const float* __restrict__ We1,                      // row 256 = dist^2 weights
    const float* __restrict__ We2, const float* __restrict__ be2,
    const float* __restrict__ Wc1, const float* __restrict__ bc1,
    const float* __restrict__ Wc2, float* __restrict__ xo)
{
    const int AW = 132;
    extern __shared__ float sm[];
    float* sA   = sm;                          // 64*132
    float* sB   = sm + 64 * AW;                // 2*32*128 = 8192
    float* sRel = sB + 8192;                   // 192
    float* sD2  = sRel + 192;                  // 64
    float* sW   = sD2 + 64;                    // 128 (We1 row 256)
    int*   sSrc = (int*)(sW + 128);            // 64
    int*   sDst = sSrc + 64;                   // 64

    int tid = threadIdx.x;
    int ty = tid >> 4, tx = tid & 15;
    int e0 = blockIdx.x * 64;

    if (tid < 64) {
        int ge = e0 + tid;
        int s = ei[ge], d = ei[Ee + ge];
        float rx = x[s * 3 + 0] - x[d * 3 + 0];
        float ry = x[s * 3 + 1] - x[d * 3 + 1];
        float rz = x[s * 3 + 2] - x[d * 3 + 2];
        sRel[tid * 3 + 0] = rx; sRel[tid * 3 + 1] = ry; sRel[tid * 3 + 2] = rz;
        sD2[tid] = rx * rx + ry * ry + rz * rz;
        sSrc[tid] = s; sDst[tid] = d;
    } else if (tid < 96) {
        int t = tid - 64;
        *(float4*)(sW + t * 4) = *(const float4*)(We1 + 256 * Hh + t * 4);
    }
    __syncthreads();

    // layer-1 output directly: sA[i] = silu(hs[src] + hd[dst] + d2 * w256)
    for (int idx = tid; idx < 64 * 32; idx += 128) {
        int i = idx >> 5, q = (idx & 31) * 4;
        int s = sSrc[i], d = sDst[i];
        float d2 = sD2[i];
        float4 a = *(const float4*)(g_hs + (size_t)s * Hh + q);
        float4 b = *(const float4*)(g_hd + (size_t)d * Hh + q);
        float4 w = *(const float4*)(sW + q);
        float* p = sA + i * AW + q;
        p[0] = silu_f(a.x + b.x + d2 * w.x);
        p[1] = silu_f(a.y + b.y + d2 * w.y);
        p[2] = silu_f(a.z + b.z + d2 * w.z);
        p[3] = silu_f(a.w + b.w + d2 * w.w);
    }
    // (first barrier inside gemm_tile covers these writes)

    unsigned long long acc2[8][4];

    // layer 2: m_ij = silu([64x128] @ We2 + be2), left in sA
    gemm_tile<AW, true>(sA, sB, We2, Hh, ty, tx, tid, acc2);
    bias_silu_store<AW>(acc2, be2, sA, ty, tx);

    // coord MLP: w = silu(m_ij @ Wc1 + bc1) . Wc2
    gemm_tile<AW, true>(sA, sB, Wc1, Hh, ty, tx, tid, acc2);

    float partial[8];
#pragma unroll
    for (int r = 0; r < 8; r++) partial[r] = 0.f;
#pragma unroll
    for (int r = 0; r < 8; r++)
#pragma unroll
        for (int cp = 0; cp < 4; cp++) {
            U64F2 u; u.u = acc2[r][cp];
            int f = colof(tx, cp);
            partial[r] += silu_f(u.f.x + bc1[f])     * Wc2[f];
            partial[r] += silu_f(u.f.y + bc1[f + 1]) * Wc2[f + 1];
        }
#pragma unroll
    for (int off = 8; off > 0; off >>= 1)
#pragma unroll
        for (int r = 0; r < 8; r++)
            partial[r] += __shfl_xor_sync(0xffffffffu, partial[r], off);

    if (tx == 0) {
#pragma unroll
        for (int r = 0; r < 8; r++) {
            int i = ty * 8 + r;
            float w = partial[r];
            int d = sDst[i];
            atomicAdd(xo + (size_t)d * 3 + 0, sRel[i * 3 + 0] * w);
            atomicAdd(xo + (size_t)d * 3 + 1, sRel[i * 3 + 1] * w);
            atomicAdd(xo + (size_t)d * 3 + 2, sRel[i * 3 + 2] * w);
        }
    }

    // msg_agg scatter: m_ij still in sA; vectorized global reductions
    for (int idx = tid; idx < 64 * 32; idx += 128) {
        int i = idx >> 5, q = (idx & 31) * 4;
        const float* p = sA + i * AW + q;
        float v0 = p[0], v1 = p[1], v2 = p[2], v3 = p[3];
        float* gp = g_msg + (size_t)sDst[i] * Hh + q;
        asm volatile("red.global.add.v4.f32 [%0], {%1, %2, %3, %4};"
                     :: "l"(gp), "f"(v0), "f"(v1), "f"(v2), "f"(v3) : "memory");
    }
}

// ---------------------------------------------------------------------------
// node kernel: h_out = h + Wn2 @ SiLU(h@Wn1_top + msg@Wn1_bot + bn1) + bn2
// Concat-GEMM split into two accumulating K=128 GEMMs -> AW=132, 3 CTAs/SM.
__global__ __launch_bounds__(128, 3) void node_kernel(
    const float* __restrict__ h,
    const float* __restrict__ Wn1, const float* __restrict__ bn1,
    const float* __restrict__ Wn2, const float* __restrict__ bn2,
    float* __restrict__ ho)
{
    const int AW = 132;
    extern __shared__ float sm[];
    float* sA = sm;                 // 64 * 132
    float* sB = sm + 64 * AW;       // 8192
    int tid = threadIdx.x;
    int ty = tid >> 4, tx = tid & 15;
    int n0 = blockIdx.x * 64;

    // A := h tile
    for (int idx = tid; idx < 64 * 32; idx += 128) {
        int i = idx >> 5, q = (idx & 31) * 4;
        int n = n0 + i;
        float4 v = make_float4(0.f, 0.f, 0.f, 0.f);
        if (n < Nn) v = *(const float4*)(h + (size_t)n * Hh + q);
        *(float4*)(sA + i * AW + q) = v;
    }

    unsigned long long acc2[8][4];
    gemm_tile<AW, true>(sA, sB, Wn1, Hh, ty, tx, tid, acc2);        // h @ Wn1_top

    // A := msg tile (safe: last barrier in gemm_tile is after all sA reads)
    for (int idx = tid; idx < 64 * 32; idx += 128) {
        int i = idx >> 5, q = (idx & 31) * 4;
        int n = n0 + i;
        float4 v = make_float4(0.f, 0.f, 0.f, 0.f);
        if (n < Nn) v = *(const float4*)(g_msg + (size_t)n * Hh + q);
        *(float4*)(sA + i * AW + q) = v;
    }
    gemm_tile<AW, false>(sA, sB, Wn1 + Hh * Hh, Hh, ty, tx, tid, acc2);  // += msg @ Wn1_bot

    bias_silu_store<AW>(acc2, bn1, sA, ty, tx);
    gemm_tile<AW, true>(sA, sB, Wn2, Hh, ty, tx, tid, acc2);

#pragma unroll
    for (int r = 0; r < 8; r++) {
        int n = n0 + ty * 8 + r;
        if (n < Nn) {
#pragma unroll
            for (int cp = 0; cp < 4; cp++) {
                U64F2 u; u.u = acc2[r][cp];
                int f = colof(tx, cp);
                float2 o;
                o.x = u.f.x + bn2[f]     + h[(size_t)n * Hh + f];
                o.y = u.f.y + bn2[f + 1] + h[(size_t)n * Hh + f + 1];
                *(float2*)(ho + (size_t)n * Hh + f) = o;
            }
        }
    }
}

// ---------------------------------------------------------------------------
static const int PRE_SMEM  = (64 * 132 + 8192) * 4;                         // 66560
static const int EDGE_SMEM = (64 * 132 + 8192 + 192 + 64 + 128 + 128) * 4;  // 68608
static const int NODE_SMEM = (64 * 132 + 8192) * 4;                         // 66560

extern "C" void kernel_launch(void* const* d_in, const int* in_sizes, int n_in,
                              void* d_out, int out_size) {
    const float* h   = (const float*)d_in[0];
    const float* x   = (const float*)d_in[1];
    const int*   ei  = (const int*)d_in[2];
    const float* We1 = (const float*)d_in[3];
    const float* be1 = (const float*)d_in[4];
    const float* We2 = (const float*)d_in[5];
    const float* be2 = (const float*)d_in[6];
    const float* Wc1 = (const float*)d_in[7];
    const float* bc1 = (const float*)d_in[8];
    const float* Wc2 = (const float*)d_in[9];
    const float* Wn1 = (const float*)d_in[10];
    const float* bn1 = (const float*)d_in[11];
    const float* Wn2 = (const float*)d_in[12];
    const float* bn2 = (const float*)d_in[13];

    float* out = (float*)d_out;
    float* ho = out;                         // h_out: N*H
    float* xo = out + (size_t)Nn * Hh;       // x_out: N*3

    cudaFuncSetAttribute(pre_kernel,  cudaFuncAttributeMaxDynamicSharedMemorySize, PRE_SMEM);
    cudaFuncSetAttribute(edge_kernel, cudaFuncAttributeMaxDynamicSharedMemorySize, EDGE_SMEM);
    cudaFuncSetAttribute(node_kernel, cudaFuncAttributeMaxDynamicSharedMemorySize, NODE_SMEM);

    init_kernel<<<(Nn * Hh + 255) / 256, 256>>>(x, xo);
    pre_kernel<<<(Nn + 63) / 64, 128, PRE_SMEM>>>(h, We1, be1);
    edge_kernel<<<Ee / 64, 128, EDGE_SMEM>>>(x, ei, We1, We2, be2, Wc1, bc1, Wc2, xo);
    node_kernel<<<(Nn + 63) / 64, 128, NODE_SMEM>>>(h, Wn1, bn1, Wn2, bn2, ho);
}